// round 1
// baseline (speedup 1.0000x reference)
#include <cuda_runtime.h>

#define NN 100000
#define EE 1600000
#define CC 16
#define HH 32
#define NLAY 8
#define TPB 256
#define MAXIT 10

// ---------------- device scratch (static allocs are allowed) ----------------
__device__ unsigned int        g_mkey[NN];   // ordered-key max of raw logits per dst node
__device__ double              g_ssum[NN];   // sum of exp per dst node
__device__ float               g_tmp[EE];    // raw logits, then exp values
__device__ float               g_score[EE];  // running score
__device__ unsigned long long  g_packs[NN];  // (score_bits<<32)|(E-eid)  max over src segment
__device__ unsigned long long  g_packd[NN];  // same over dst segment
__device__ int                 g_maxidx[NN];
__device__ unsigned char       g_nrem[NN];
__device__ unsigned char       g_rm[NN];
__device__ unsigned char       g_erem[EE];
__device__ int                 g_cnt[MAXIT]; // remaining-node count per iteration

// ordered key for signed floats (monotonic in float order)
__device__ __forceinline__ unsigned int fkey(float f) {
    unsigned int b = __float_as_uint(f);
    return (b & 0x80000000u) ? ~b : (b | 0x80000000u);
}
__device__ __forceinline__ float fkey_inv(unsigned int k) {
    unsigned int b = (k & 0x80000000u) ? (k ^ 0x80000000u) : ~k;
    return __uint_as_float(b);
}

// ---------------- init ----------------
__global__ void k_init() {
    int i = blockIdx.x * blockDim.x + threadIdx.x;
    int stride = gridDim.x * blockDim.x;
    for (int n = i; n < NN; n += stride) {
        g_mkey[n] = 0u;          // below every real key
        g_ssum[n] = 0.0;
        g_packs[n] = 0ull;       // score=0.0f, eid=E  (matches empty-segment fill)
        g_packd[n] = 0ull;
        g_nrem[n] = 1;
        g_rm[n] = 0;
    }
    for (int e = i; e < EE; e += stride) g_erem[e] = 1;
    if (i < MAXIT) g_cnt[i] = 0;
}

// ---------------- edge MLP (fp32, weights in SMEM) + dst max accumulation ----------------
__global__ void __launch_bounds__(TPB, 2)
k_mlp(const float* __restrict__ x, const int* __restrict__ ei,
      const float* __restrict__ Wh, const float* __restrict__ bh,
      const float* __restrict__ Wo, const float* __restrict__ bo) {
    __shared__ float Wsh[NLAY * HH * HH];
    __shared__ float bsh[NLAY * HH];
    __shared__ float Wosh[HH];
    __shared__ float bosh;
    for (int i = threadIdx.x; i < NLAY * HH * HH; i += blockDim.x) Wsh[i] = Wh[i];
    for (int i = threadIdx.x; i < NLAY * HH; i += blockDim.x) bsh[i] = bh[i];
    if (threadIdx.x < HH) Wosh[threadIdx.x] = Wo[threadIdx.x];
    if (threadIdx.x == 0) bosh = bo[0];
    __syncthreads();

    int e = blockIdx.x * blockDim.x + threadIdx.x;
    if (e >= EE) return;
    int s = ei[e], d = ei[EE + e];

    float h[HH];
    const float4* xs = (const float4*)(x + (size_t)s * CC);
    const float4* xd = (const float4*)(x + (size_t)d * CC);
#pragma unroll
    for (int q = 0; q < 4; q++) {
        float4 v = xs[q];
        h[4 * q + 0] = v.x; h[4 * q + 1] = v.y; h[4 * q + 2] = v.z; h[4 * q + 3] = v.w;
    }
#pragma unroll
    for (int q = 0; q < 4; q++) {
        float4 v = xd[q];
        h[16 + 4 * q + 0] = v.x; h[16 + 4 * q + 1] = v.y; h[16 + 4 * q + 2] = v.z; h[16 + 4 * q + 3] = v.w;
    }

#pragma unroll 1
    for (int l = 0; l < NLAY; l++) {
        float a[HH];
#pragma unroll
        for (int j = 0; j < HH; j++) a[j] = bsh[l * HH + j];
        const float* Wl = Wsh + l * HH * HH;
#pragma unroll
        for (int k = 0; k < HH; k++) {
            float hk = h[k];
            const float4* w4 = (const float4*)(Wl + k * HH);
#pragma unroll
            for (int j = 0; j < HH / 4; j++) {
                float4 w = w4[j];
                a[4 * j + 0] = fmaf(hk, w.x, a[4 * j + 0]);
                a[4 * j + 1] = fmaf(hk, w.y, a[4 * j + 1]);
                a[4 * j + 2] = fmaf(hk, w.z, a[4 * j + 2]);
                a[4 * j + 3] = fmaf(hk, w.w, a[4 * j + 3]);
            }
        }
#pragma unroll
        for (int j = 0; j < HH; j++) h[j] = fmaxf(a[j], 0.0f);
    }
    float acc = bosh;
#pragma unroll
    for (int k = 0; k < HH; k++) acc = fmaf(h[k], Wosh[k], acc);

    g_tmp[e] = acc;
    atomicMax(&g_mkey[d], fkey(acc));
}

// ---------------- exp + segment sum ----------------
__global__ void k_exp(const int* __restrict__ ei) {
    int e = blockIdx.x * blockDim.x + threadIdx.x;
    if (e >= EE) return;
    int d = ei[EE + e];
    float m = fkey_inv(g_mkey[d]);           // segment nonempty here, always finite
    float ex = expf(g_tmp[e] - m);
    g_tmp[e] = ex;
    atomicAdd(&g_ssum[d], (double)ex);
}

// ---------------- softmax finalize + first-iteration pack accumulation ----------------
__global__ void k_soft(const int* __restrict__ ei) {
    int e = blockIdx.x * blockDim.x + threadIdx.x;
    if (e >= EE) return;
    int s = ei[e], d = ei[EE + e];
    float sc = g_tmp[e] / (float)g_ssum[d] + 0.5f;   // score >= 0 always
    g_score[e] = sc;
    unsigned long long pk =
        ((unsigned long long)__float_as_uint(sc) << 32) | (unsigned int)(EE - e);
    atomicMax(&g_packs[s], pk);
    atomicMax(&g_packd[d], pk);
}

// done(t) <=> some earlier iteration's remaining count <= 5000.
// Frozen iterations leave g_cnt at 0 (<=5000) so the chain stays done.
__device__ __forceinline__ bool iter_done(int t) {
    return (t > 0) && (g_cnt[t - 1] <= 5000);
}

// ---------------- merge iteration: node phase A (max_idx, reset packs/rm) ----------------
__global__ void k_node_a(const int* __restrict__ ei, int t) {
    if (iter_done(t)) return;
    int n = blockIdx.x * blockDim.x + threadIdx.x;
    if (n >= NN) return;
    unsigned long long p0 = g_packs[n], p1 = g_packd[n];
    g_packs[n] = 0ull; g_packd[n] = 0ull;
    g_rm[n] = 0;
    float ms0 = __uint_as_float((unsigned int)(p0 >> 32));
    float ms1 = __uint_as_float((unsigned int)(p1 >> 32));
    int mi = 0;
    if (ms1 > ms0) {
        int eid = EE - (int)(unsigned int)(p1 & 0xFFFFFFFFull);
        eid = min(eid, EE - 1);
        mi = ei[eid];            // src[am1]
    } else if (ms0 > ms1) {
        int eid = EE - (int)(unsigned int)(p0 & 0xFFFFFFFFull);
        eid = min(eid, EE - 1);
        mi = ei[EE + eid];       // dst[am0]
    }
    g_maxidx[n] = mi;
}

// ---------------- merge iteration: edge phase B (mutual match, mark removals) ----------------
__global__ void k_edge_b(const int* __restrict__ ei, int t) {
    if (iter_done(t)) return;
    int e = blockIdx.x * blockDim.x + threadIdx.x;
    if (e >= EE) return;
    int s = ei[e], d = ei[EE + e];
    bool match = (g_maxidx[d] == s) && (g_maxidx[s] == d) && g_nrem[s] && g_nrem[d];
    if (match) {
        g_erem[e] = 0;
        g_rm[s] = 1;
        g_rm[d] = 1;
    }
}

// ---------------- merge iteration: node phase B (update nodes_rem + count) ----------------
__global__ void k_node_b(int t) {
    if (iter_done(t)) return;
    int n = blockIdx.x * blockDim.x + threadIdx.x;
    if (n >= NN) return;
    unsigned char nr = g_nrem[n] & (unsigned char)(g_rm[n] ^ 1);
    g_nrem[n] = nr;
    if (nr) atomicAdd(&g_cnt[t], 1);
}

// ---------------- merge iteration: edge phase C (zero scores; accumulate next packs) ----------------
__global__ void k_edge_c(const int* __restrict__ ei, int t) {
    if (iter_done(t)) return;
    int e = blockIdx.x * blockDim.x + threadIdx.x;
    if (e >= EE) return;
    int s = ei[e], d = ei[EE + e];
    float sc = g_score[e];
    bool keep = g_nrem[s] && g_nrem[d];
    sc = keep ? sc : 0.0f;
    g_score[e] = sc;
    // accumulate argmax packs for the NEXT iteration, unless it will be frozen
    if (t < MAXIT - 1 && g_cnt[t] > 5000) {
        unsigned long long pk =
            ((unsigned long long)__float_as_uint(sc) << 32) | (unsigned int)(EE - e);
        atomicMax(&g_packs[s], pk);
        atomicMax(&g_packd[d], pk);
    }
}

// ---------------- output: [score(E) | edges_remaining(E) | nodes_remaining(N)] as f32 ----------------
__global__ void k_out(float* __restrict__ out) {
    int i = blockIdx.x * blockDim.x + threadIdx.x;
    int stride = gridDim.x * blockDim.x;
    for (int e = i; e < EE; e += stride) {
        out[e] = g_score[e];
        out[EE + e] = g_erem[e] ? 1.0f : 0.0f;
    }
    for (int n = i; n < NN; n += stride) {
        out[2 * EE + n] = g_nrem[n] ? 1.0f : 0.0f;
    }
}

extern "C" void kernel_launch(void* const* d_in, const int* in_sizes, int n_in,
                              void* d_out, int out_size) {
    const float* x  = (const float*)d_in[0];
    const int*   ei = (const int*)d_in[1];
    // d_in[2] = batch (unused, all zeros)
    const float* Wh = (const float*)d_in[3];
    const float* bh = (const float*)d_in[4];
    const float* Wo = (const float*)d_in[5];
    const float* bo = (const float*)d_in[6];
    float* out = (float*)d_out;

    const int eblocks = (EE + TPB - 1) / TPB;
    const int nblocks = (NN + TPB - 1) / TPB;

    k_init<<<2048, TPB>>>();
    k_mlp<<<eblocks, TPB>>>(x, ei, Wh, bh, Wo, bo);
    k_exp<<<eblocks, TPB>>>(ei);
    k_soft<<<eblocks, TPB>>>(ei);
    for (int t = 0; t < MAXIT; t++) {
        k_node_a<<<nblocks, TPB>>>(ei, t);
        k_edge_b<<<eblocks, TPB>>>(ei, t);
        k_node_b<<<nblocks, TPB>>>(t);
        k_edge_c<<<eblocks, TPB>>>(ei, t);
    }
    k_out<<<2048, TPB>>>(out);
}

// round 2
// speedup vs baseline: 1.0607x; 1.0607x over previous
#include <cuda_runtime.h>

#define NN 100000
#define EE 1600000
#define CC 16
#define HH 32
#define NLAY 8
#define TPB 256
#define MAXIT 10
#define THRESH 5000   // count <= 5000  <=>  ratio <= 0.05 (exact in fp32)

// ---------------- device scratch ----------------
__device__ unsigned int        g_mkey[NN];   // ordered-key max of raw logits per dst node
__device__ double              g_ssum[NN];   // sum of exp per dst node
__device__ float               g_tmp[EE];    // raw logits, then exp values
__device__ float               g_score[EE];  // softmax score (immutable after k_soft)
__device__ unsigned long long  g_packs[NN];  // (score_bits<<32)|(E-eid)  max over src segment
__device__ unsigned long long  g_packd[NN];  // same over dst segment
__device__ int                 g_maxidx[NN];
__device__ int                 g_part[NN];   // merge partner (-1 = never removed)
__device__ unsigned char       g_nrem[NN];
__device__ unsigned char       g_rm[NN];
__device__ int                 g_cnt[MAXIT]; // remaining-node count per iteration
__device__ int                 g_lc[2];      // live-list counts (ping-pong)
__device__ int4                g_list[2][EE];// live edge records {s, d, eid, score_bits}

__device__ __forceinline__ unsigned int fkey(float f) {
    unsigned int b = __float_as_uint(f);
    return (b & 0x80000000u) ? ~b : (b | 0x80000000u);
}
__device__ __forceinline__ float fkey_inv(unsigned int k) {
    unsigned int b = (k & 0x80000000u) ? (k ^ 0x80000000u) : ~k;
    return __uint_as_float(b);
}

// done(t) <=> some earlier iteration's remaining count <= THRESH.
// Frozen iterations leave g_cnt at 0 (<=THRESH) so the chain stays done.
__device__ __forceinline__ bool iter_done(int t) {
    return (t > 0) && (g_cnt[t - 1] <= THRESH);
}

// ---------------- init ----------------
__global__ void k_init() {
    int i = blockIdx.x * blockDim.x + threadIdx.x;
    int stride = gridDim.x * blockDim.x;
    for (int n = i; n < NN; n += stride) {
        g_mkey[n] = 0u;
        g_ssum[n] = 0.0;
        g_packs[n] = 0ull;       // score=0.0f, eid=E (matches empty-segment fill)
        g_packd[n] = 0ull;
        g_nrem[n] = 1;
        g_part[n] = -1;
    }
    if (i < MAXIT) g_cnt[i] = 0;
    if (i < 2) g_lc[i] = 0;
}

// ---------------- edge MLP (fp32, weights in SMEM) + dst max accumulation ----------------
__global__ void __launch_bounds__(TPB, 2)
k_mlp(const float* __restrict__ x, const int* __restrict__ ei,
      const float* __restrict__ Wh, const float* __restrict__ bh,
      const float* __restrict__ Wo, const float* __restrict__ bo) {
    __shared__ float Wsh[NLAY * HH * HH];
    __shared__ float bsh[NLAY * HH];
    __shared__ float Wosh[HH];
    __shared__ float bosh;
    for (int i = threadIdx.x; i < NLAY * HH * HH; i += blockDim.x) Wsh[i] = Wh[i];
    for (int i = threadIdx.x; i < NLAY * HH; i += blockDim.x) bsh[i] = bh[i];
    if (threadIdx.x < HH) Wosh[threadIdx.x] = Wo[threadIdx.x];
    if (threadIdx.x == 0) bosh = bo[0];
    __syncthreads();

    int e = blockIdx.x * blockDim.x + threadIdx.x;
    if (e >= EE) return;
    int s = ei[e], d = ei[EE + e];

    float h[HH];
    const float4* xs = (const float4*)(x + (size_t)s * CC);
    const float4* xd = (const float4*)(x + (size_t)d * CC);
#pragma unroll
    for (int q = 0; q < 4; q++) {
        float4 v = xs[q];
        h[4 * q + 0] = v.x; h[4 * q + 1] = v.y; h[4 * q + 2] = v.z; h[4 * q + 3] = v.w;
    }
#pragma unroll
    for (int q = 0; q < 4; q++) {
        float4 v = xd[q];
        h[16 + 4 * q + 0] = v.x; h[16 + 4 * q + 1] = v.y; h[16 + 4 * q + 2] = v.z; h[16 + 4 * q + 3] = v.w;
    }

#pragma unroll 1
    for (int l = 0; l < NLAY; l++) {
        float a[HH];
#pragma unroll
        for (int j = 0; j < HH; j++) a[j] = bsh[l * HH + j];
        const float* Wl = Wsh + l * HH * HH;
#pragma unroll
        for (int k = 0; k < HH; k++) {
            float hk = h[k];
            const float4* w4 = (const float4*)(Wl + k * HH);
#pragma unroll
            for (int j = 0; j < HH / 4; j++) {
                float4 w = w4[j];
                a[4 * j + 0] = fmaf(hk, w.x, a[4 * j + 0]);
                a[4 * j + 1] = fmaf(hk, w.y, a[4 * j + 1]);
                a[4 * j + 2] = fmaf(hk, w.z, a[4 * j + 2]);
                a[4 * j + 3] = fmaf(hk, w.w, a[4 * j + 3]);
            }
        }
#pragma unroll
        for (int j = 0; j < HH; j++) h[j] = fmaxf(a[j], 0.0f);
    }
    float acc = bosh;
#pragma unroll
    for (int k = 0; k < HH; k++) acc = fmaf(h[k], Wosh[k], acc);

    g_tmp[e] = acc;
    atomicMax(&g_mkey[d], fkey(acc));
}

// ---------------- exp + segment sum ----------------
__global__ void k_exp(const int* __restrict__ ei) {
    int e = blockIdx.x * blockDim.x + threadIdx.x;
    if (e >= EE) return;
    int d = ei[EE + e];
    float m = fkey_inv(g_mkey[d]);
    float ex = expf(g_tmp[e] - m);
    g_tmp[e] = ex;
    atomicAdd(&g_ssum[d], (double)ex);
}

// ---------------- softmax finalize + iteration-0 pack accumulation ----------------
__global__ void k_soft(const int* __restrict__ ei) {
    int e = blockIdx.x * blockDim.x + threadIdx.x;
    if (e >= EE) return;
    int s = ei[e], d = ei[EE + e];
    float sc = g_tmp[e] / (float)g_ssum[d] + 0.5f;   // always > 0.5
    g_score[e] = sc;
    unsigned long long pk =
        ((unsigned long long)__float_as_uint(sc) << 32) | (unsigned int)(EE - e);
    atomicMax(&g_packs[s], pk);
    atomicMax(&g_packd[d], pk);
}

// ---------------- merge: node phase A (max_idx from packs; reset packs/list counter) ----
__global__ void k_node_a(const int* __restrict__ ei, int t) {
    if (iter_done(t)) return;
    int n = blockIdx.x * blockDim.x + threadIdx.x;
    if (n == 0) g_lc[(t + 1) & 1] = 0;
    if (n >= NN) return;
    unsigned long long p0 = g_packs[n], p1 = g_packd[n];
    g_packs[n] = 0ull; g_packd[n] = 0ull;
    float ms0 = __uint_as_float((unsigned int)(p0 >> 32));
    float ms1 = __uint_as_float((unsigned int)(p1 >> 32));
    int mi = 0;
    if (ms1 > ms0) {
        int eid = EE - (int)(unsigned int)(p1 & 0xFFFFFFFFull);
        eid = min(eid, EE - 1);
        mi = ei[eid];            // src[am1]
    } else if (ms0 > ms1) {
        int eid = EE - (int)(unsigned int)(p0 & 0xFFFFFFFFull);
        eid = min(eid, EE - 1);
        mi = ei[EE + eid];       // dst[am0]
    }
    g_maxidx[n] = mi;
}

// ---------------- merge: node phase B (mutual-match removal flag, snapshot-safe) ------
__global__ void k_node_rm(int t) {
    if (iter_done(t)) return;
    int n = blockIdx.x * blockDim.x + threadIdx.x;
    if (n >= NN) return;
    int v = g_maxidx[n];
    bool rm = g_nrem[n] && g_nrem[v] && (g_maxidx[v] == n);
    g_rm[n] = rm ? 1 : 0;
}

// ---------------- merge: node phase C (apply removal, record partner, count) ----------
__global__ void k_node_apply(int t) {
    if (iter_done(t)) return;
    int n = blockIdx.x * blockDim.x + threadIdx.x;
    int surv = 0;
    if (n < NN) {
        unsigned char nr = g_nrem[n];
        if (g_rm[n]) {
            nr = 0;
            g_nrem[n] = 0;
            g_part[n] = g_maxidx[n];
        }
        surv = nr ? 1 : 0;
    }
    // warp-aggregated count
    unsigned m = __ballot_sync(0xffffffffu, surv);
    if ((threadIdx.x & 31) == 0 && m)
        atomicAdd(&g_cnt[t], __popc(m));
}

// ---------------- merge: edge pass (compact live list + accumulate next packs) --------
__global__ void k_edge(const int* __restrict__ ei, int t) {
    if (iter_done(t)) return;
    // if the loop freezes after this iteration, nothing downstream reads packs/list
    if (t == MAXIT - 1 || g_cnt[t] <= THRESH) return;

    int total = (t == 0) ? EE : g_lc[t & 1];
    int lane = threadIdx.x & 31;
    int stride = gridDim.x * blockDim.x;
    int start = blockIdx.x * blockDim.x + threadIdx.x;
    int iters = (total + stride - 1) / stride;
    int outp = (t + 1) & 1;

    for (int it = 0; it < iters; it++) {
        int i = start + it * stride;
        bool inb = i < total;
        int4 rec;
        if (inb) {
            if (t == 0) {
                rec.x = ei[i];
                rec.y = ei[EE + i];
                rec.z = i;
                rec.w = __float_as_int(g_score[i]);
            } else {
                rec = g_list[t & 1][i];
            }
        }
        bool live = inb && g_nrem[rec.x] && g_nrem[rec.y];
        unsigned mask = __ballot_sync(0xffffffffu, live);
        if (mask) {
            int leader = __ffs(mask) - 1;
            int base;
            if (lane == leader) base = atomicAdd(&g_lc[outp], __popc(mask));
            base = __shfl_sync(0xffffffffu, base, leader);
            if (live) {
                int off = __popc(mask & ((1u << lane) - 1));
                g_list[outp][base + off] = rec;
                unsigned long long pk =
                    ((unsigned long long)(unsigned int)rec.w << 32) |
                    (unsigned int)(EE - rec.z);
                atomicMax(&g_packs[rec.x], pk);
                atomicMax(&g_packd[rec.y], pk);
            }
        }
    }
}

// ---------------- output: [score(E) | edges_remaining(E) | nodes_remaining(N)] --------
__global__ void k_out(const int* __restrict__ ei, float* __restrict__ out) {
    int i = blockIdx.x * blockDim.x + threadIdx.x;
    int stride = gridDim.x * blockDim.x;
    for (int e = i; e < EE; e += stride) {
        int s = ei[e], d = ei[EE + e];
        bool live = g_nrem[s] && g_nrem[d];
        out[e] = live ? g_score[e] : 0.0f;
        bool removed = (g_part[s] == d) && (g_part[d] == s);
        out[EE + e] = removed ? 0.0f : 1.0f;
    }
    for (int n = i; n < NN; n += stride) {
        out[2 * EE + n] = g_nrem[n] ? 1.0f : 0.0f;
    }
}

extern "C" void kernel_launch(void* const* d_in, const int* in_sizes, int n_in,
                              void* d_out, int out_size) {
    const float* x  = (const float*)d_in[0];
    const int*   ei = (const int*)d_in[1];
    // d_in[2] = batch (unused, all zeros)
    const float* Wh = (const float*)d_in[3];
    const float* bh = (const float*)d_in[4];
    const float* Wo = (const float*)d_in[5];
    const float* bo = (const float*)d_in[6];
    float* out = (float*)d_out;

    const int eblocks = (EE + TPB - 1) / TPB;
    const int nblocks = (NN + TPB - 1) / TPB;

    k_init<<<1024, TPB>>>();
    k_mlp<<<eblocks, TPB>>>(x, ei, Wh, bh, Wo, bo);
    k_exp<<<eblocks, TPB>>>(ei);
    k_soft<<<eblocks, TPB>>>(ei);
    for (int t = 0; t < MAXIT; t++) {
        k_node_a<<<nblocks, TPB>>>(ei, t);
        k_node_rm<<<nblocks, TPB>>>(t);
        k_node_apply<<<nblocks, TPB>>>(t);
        k_edge<<<2048, TPB>>>(ei, t);
    }
    k_out<<<2048, TPB>>>(ei, out);
}

// round 3
// speedup vs baseline: 1.1503x; 1.0845x over previous
#include <cuda_runtime.h>

#define NN 100000
#define EE 1600000
#define CC 16
#define HH 32
#define NLAY 8
#define TPB 256
#define MAXIT 10
#define THRESH 5000   // count <= 5000  <=>  ratio <= 0.05 (exact in fp32)

typedef unsigned long long u64;

// ---------------- device scratch ----------------
__device__ unsigned int        g_mkey[NN];
__device__ double              g_ssum[NN];
__device__ float               g_tmp[EE];
__device__ float               g_score[EE];
__device__ unsigned long long  g_packs[NN];
__device__ unsigned long long  g_packd[NN];
__device__ int                 g_maxidx[NN];
__device__ int                 g_part[NN];
__device__ unsigned char       g_nrem[NN];
__device__ unsigned char       g_rm[NN];
__device__ int                 g_cnt[MAXIT];
__device__ int                 g_lc[2];
__device__ int4                g_list[2][EE];
__device__ float               g_P[NN * HH];   // x @ W0[:16] + b0  (src half)
__device__ float               g_Q[NN * HH];   // x @ W0[16:]       (dst half)

__device__ __forceinline__ unsigned int fkey(float f) {
    unsigned int b = __float_as_uint(f);
    return (b & 0x80000000u) ? ~b : (b | 0x80000000u);
}
__device__ __forceinline__ float fkey_inv(unsigned int k) {
    unsigned int b = (k & 0x80000000u) ? (k ^ 0x80000000u) : ~k;
    return __uint_as_float(b);
}

__device__ __forceinline__ u64 pack2(float a, float b) {
    u64 r; asm("mov.b64 %0, {%1, %2};" : "=l"(r) : "f"(a), "f"(b)); return r;
}
__device__ __forceinline__ void unpack2(u64 v, float& a, float& b) {
    asm("mov.b64 {%0, %1}, %2;" : "=f"(a), "=f"(b) : "l"(v));
}
__device__ __forceinline__ u64 fma2(u64 a, u64 b, u64 c) {
    u64 d; asm("fma.rn.f32x2 %0, %1, %2, %3;" : "=l"(d) : "l"(a), "l"(b), "l"(c)); return d;
}

__device__ __forceinline__ bool iter_done(int t) {
    return (t > 0) && (g_cnt[t - 1] <= THRESH);
}

// ---------------- init ----------------
__global__ void k_init() {
    int i = blockIdx.x * blockDim.x + threadIdx.x;
    int stride = gridDim.x * blockDim.x;
    for (int n = i; n < NN; n += stride) {
        g_mkey[n] = 0u;
        g_ssum[n] = 0.0;
        g_packs[n] = 0ull;
        g_packd[n] = 0ull;
        g_nrem[n] = 1;
        g_rm[n] = 0;
        g_part[n] = -1;
    }
    if (i < MAXIT) g_cnt[i] = 0;
    if (i < 2) g_lc[i] = 0;
}

// ---------------- per-node layer-1 precompute ----------------
__global__ void __launch_bounds__(TPB)
k_pre(const float* __restrict__ x, const float* __restrict__ Wh,
      const float* __restrict__ bh) {
    __shared__ __align__(16) float W0[HH * HH];
    __shared__ float b0[HH];
    for (int i = threadIdx.x; i < HH * HH; i += blockDim.x) W0[i] = Wh[i];
    if (threadIdx.x < HH) b0[threadIdx.x] = bh[threadIdx.x];
    __syncthreads();

    int n = blockIdx.x * blockDim.x + threadIdx.x;
    if (n >= NN) return;

    float xv[CC];
    const float4* xp = (const float4*)(x + (size_t)n * CC);
#pragma unroll
    for (int q = 0; q < 4; q++) {
        float4 v = xp[q];
        xv[4 * q] = v.x; xv[4 * q + 1] = v.y; xv[4 * q + 2] = v.z; xv[4 * q + 3] = v.w;
    }

    float a[HH];
#pragma unroll
    for (int j = 0; j < HH; j++) a[j] = b0[j];
#pragma unroll
    for (int k = 0; k < CC; k++) {
        float xk = xv[k];
        const float4* w4 = (const float4*)(W0 + k * HH);
#pragma unroll
        for (int j = 0; j < HH / 4; j++) {
            float4 w = w4[j];
            a[4 * j] = fmaf(xk, w.x, a[4 * j]);
            a[4 * j + 1] = fmaf(xk, w.y, a[4 * j + 1]);
            a[4 * j + 2] = fmaf(xk, w.z, a[4 * j + 2]);
            a[4 * j + 3] = fmaf(xk, w.w, a[4 * j + 3]);
        }
    }
    float4* Pp = (float4*)(g_P + (size_t)n * HH);
#pragma unroll
    for (int j = 0; j < HH / 4; j++)
        Pp[j] = make_float4(a[4 * j], a[4 * j + 1], a[4 * j + 2], a[4 * j + 3]);

#pragma unroll
    for (int j = 0; j < HH; j++) a[j] = 0.0f;
#pragma unroll
    for (int k = 0; k < CC; k++) {
        float xk = xv[k];
        const float4* w4 = (const float4*)(W0 + (CC + k) * HH);
#pragma unroll
        for (int j = 0; j < HH / 4; j++) {
            float4 w = w4[j];
            a[4 * j] = fmaf(xk, w.x, a[4 * j]);
            a[4 * j + 1] = fmaf(xk, w.y, a[4 * j + 1]);
            a[4 * j + 2] = fmaf(xk, w.z, a[4 * j + 2]);
            a[4 * j + 3] = fmaf(xk, w.w, a[4 * j + 3]);
        }
    }
    float4* Qp = (float4*)(g_Q + (size_t)n * HH);
#pragma unroll
    for (int j = 0; j < HH / 4; j++)
        Qp[j] = make_float4(a[4 * j], a[4 * j + 1], a[4 * j + 2], a[4 * j + 3]);
}

// ---------------- edge MLP layers 2..8 with packed f32x2 ----------------
__global__ void __launch_bounds__(TPB)
k_mlp(const int* __restrict__ ei,
      const float* __restrict__ Wh, const float* __restrict__ bh,
      const float* __restrict__ Wo, const float* __restrict__ bo) {
    __shared__ __align__(16) float Wsh[(NLAY - 1) * HH * HH];  // layers 1..7
    __shared__ __align__(16) float bsh[(NLAY - 1) * HH];
    __shared__ float Wosh[HH];
    __shared__ float bosh;
    for (int i = threadIdx.x; i < (NLAY - 1) * HH * HH; i += blockDim.x)
        Wsh[i] = Wh[HH * HH + i];
    for (int i = threadIdx.x; i < (NLAY - 1) * HH; i += blockDim.x)
        bsh[i] = bh[HH + i];
    if (threadIdx.x < HH) Wosh[threadIdx.x] = Wo[threadIdx.x];
    if (threadIdx.x == 0) bosh = bo[0];
    __syncthreads();

    int e = blockIdx.x * blockDim.x + threadIdx.x;
    if (e >= EE) return;
    int s = ei[e], d = ei[EE + e];

    float h[HH];
    const float4* Pp = (const float4*)(g_P + (size_t)s * HH);
    const float4* Qp = (const float4*)(g_Q + (size_t)d * HH);
#pragma unroll
    for (int q = 0; q < HH / 4; q++) {
        float4 p = Pp[q];
        float4 qq = Qp[q];
        h[4 * q] = fmaxf(p.x + qq.x, 0.0f);
        h[4 * q + 1] = fmaxf(p.y + qq.y, 0.0f);
        h[4 * q + 2] = fmaxf(p.z + qq.z, 0.0f);
        h[4 * q + 3] = fmaxf(p.w + qq.w, 0.0f);
    }

#pragma unroll 1
    for (int l = 0; l < NLAY - 1; l++) {
        u64 acc[HH / 2];
        const u64* b2 = (const u64*)(bsh + l * HH);
#pragma unroll
        for (int j = 0; j < HH / 2; j++) acc[j] = b2[j];
        const ulonglong2* w2 = (const ulonglong2*)(Wsh + l * HH * HH);
#pragma unroll
        for (int k = 0; k < HH; k++) {
            u64 hk2 = pack2(h[k], h[k]);
#pragma unroll
            for (int jj = 0; jj < HH / 4; jj++) {
                ulonglong2 W = w2[k * (HH / 4) + jj];
                acc[2 * jj] = fma2(hk2, W.x, acc[2 * jj]);
                acc[2 * jj + 1] = fma2(hk2, W.y, acc[2 * jj + 1]);
            }
        }
#pragma unroll
        for (int j = 0; j < HH / 2; j++) {
            float a0, a1;
            unpack2(acc[j], a0, a1);
            h[2 * j] = fmaxf(a0, 0.0f);
            h[2 * j + 1] = fmaxf(a1, 0.0f);
        }
    }

    float accs = bosh;
#pragma unroll
    for (int k = 0; k < HH; k++) accs = fmaf(h[k], Wosh[k], accs);

    g_tmp[e] = accs;
    atomicMax(&g_mkey[d], fkey(accs));
}

// ---------------- exp + segment sum ----------------
__global__ void k_exp(const int* __restrict__ ei) {
    int e = blockIdx.x * blockDim.x + threadIdx.x;
    if (e >= EE) return;
    int d = ei[EE + e];
    float m = fkey_inv(g_mkey[d]);
    float ex = expf(g_tmp[e] - m);
    g_tmp[e] = ex;
    atomicAdd(&g_ssum[d], (double)ex);
}

// ---------------- softmax finalize + iteration-0 pack accumulation ----------------
__global__ void k_soft(const int* __restrict__ ei) {
    int e = blockIdx.x * blockDim.x + threadIdx.x;
    if (e >= EE) return;
    int s = ei[e], d = ei[EE + e];
    float sc = g_tmp[e] / (float)g_ssum[d] + 0.5f;
    g_score[e] = sc;
    unsigned long long pk =
        ((unsigned long long)__float_as_uint(sc) << 32) | (unsigned int)(EE - e);
    atomicMax(&g_packs[s], pk);
    atomicMax(&g_packd[d], pk);
}

// ---------------- merge A: apply pending removal; maxidx from packs ----------------
__global__ void k_A(const int* __restrict__ ei, int t) {
    if (iter_done(t)) return;
    int n = blockIdx.x * blockDim.x + threadIdx.x;
    if (n == 0) g_lc[(t + 1) & 1] = 0;
    if (n >= NN) return;
    if (g_rm[n]) g_nrem[n] = 0;     // commit iteration t-1 (rm==0 at t=0)
    unsigned long long p0 = g_packs[n], p1 = g_packd[n];
    g_packs[n] = 0ull; g_packd[n] = 0ull;
    float ms0 = __uint_as_float((unsigned int)(p0 >> 32));
    float ms1 = __uint_as_float((unsigned int)(p1 >> 32));
    int mi = 0;
    if (ms1 > ms0) {
        int eid = EE - (int)(unsigned int)(p1 & 0xFFFFFFFFull);
        eid = min(eid, EE - 1);
        mi = ei[eid];
    } else if (ms0 > ms1) {
        int eid = EE - (int)(unsigned int)(p0 & 0xFFFFFFFFull);
        eid = min(eid, EE - 1);
        mi = ei[EE + eid];
    }
    g_maxidx[n] = mi;
}

// ---------------- merge B: mutual-match flag + partner + survivor count ----------------
__global__ void k_B(int t) {
    if (iter_done(t)) return;
    int n = blockIdx.x * blockDim.x + threadIdx.x;
    int surv = 0;
    if (n < NN) {
        int v = g_maxidx[n];
        bool nr = g_nrem[n];
        bool rm = nr && g_nrem[v] && (g_maxidx[v] == n);
        g_rm[n] = rm ? 1 : 0;
        if (rm) g_part[n] = v;
        surv = (nr && !rm) ? 1 : 0;
    }
    unsigned m = __ballot_sync(0xffffffffu, surv);
    if ((threadIdx.x & 31) == 0 && m)
        atomicAdd(&g_cnt[t], __popc(m));
}

// ---------------- merge E: compact live list + accumulate next packs ----------------
__global__ void k_E(const int* __restrict__ ei, int t) {
    if (iter_done(t)) return;
    if (t == MAXIT - 1 || g_cnt[t] <= THRESH) return;

    int total = (t == 0) ? EE : g_lc[t & 1];
    int lane = threadIdx.x & 31;
    int stride = gridDim.x * blockDim.x;
    int start = blockIdx.x * blockDim.x + threadIdx.x;
    int iters = (total + stride - 1) / stride;
    int outp = (t + 1) & 1;

    for (int it = 0; it < iters; it++) {
        int i = start + it * stride;
        bool inb = i < total;
        int4 rec;
        if (inb) {
            if (t == 0) {
                rec.x = ei[i];
                rec.y = ei[EE + i];
                rec.z = i;
                rec.w = __float_as_int(g_score[i]);
            } else {
                rec = g_list[t & 1][i];
            }
        }
        bool live = inb && g_nrem[rec.x] && !g_rm[rec.x]
                        && g_nrem[rec.y] && !g_rm[rec.y];
        unsigned mask = __ballot_sync(0xffffffffu, live);
        if (mask) {
            int leader = __ffs(mask) - 1;
            int base;
            if (lane == leader) base = atomicAdd(&g_lc[outp], __popc(mask));
            base = __shfl_sync(0xffffffffu, base, leader);
            if (live) {
                int off = __popc(mask & ((1u << lane) - 1));
                g_list[outp][base + off] = rec;
                unsigned long long pk =
                    ((unsigned long long)(unsigned int)rec.w << 32) |
                    (unsigned int)(EE - rec.z);
                atomicMax(&g_packs[rec.x], pk);
                atomicMax(&g_packd[rec.y], pk);
            }
        }
    }
}

// ---------------- output ----------------
__global__ void k_out(const int* __restrict__ ei, float* __restrict__ out) {
    int i = blockIdx.x * blockDim.x + threadIdx.x;
    int stride = gridDim.x * blockDim.x;
    for (int e = i; e < EE; e += stride) {
        int s = ei[e], d = ei[EE + e];
        bool live = g_nrem[s] && !g_rm[s] && g_nrem[d] && !g_rm[d];
        out[e] = live ? g_score[e] : 0.0f;
        bool removed = (g_part[s] == d) && (g_part[d] == s);
        out[EE + e] = removed ? 0.0f : 1.0f;
    }
    for (int n = i; n < NN; n += stride) {
        out[2 * EE + n] = (g_nrem[n] && !g_rm[n]) ? 1.0f : 0.0f;
    }
}

extern "C" void kernel_launch(void* const* d_in, const int* in_sizes, int n_in,
                              void* d_out, int out_size) {
    const float* x  = (const float*)d_in[0];
    const int*   ei = (const int*)d_in[1];
    const float* Wh = (const float*)d_in[3];
    const float* bh = (const float*)d_in[4];
    const float* Wo = (const float*)d_in[5];
    const float* bo = (const float*)d_in[6];
    float* out = (float*)d_out;

    const int eblocks = (EE + TPB - 1) / TPB;
    const int nblocks = (NN + TPB - 1) / TPB;

    k_init<<<1024, TPB>>>();
    k_pre<<<nblocks, TPB>>>(x, Wh, bh);
    k_mlp<<<eblocks, TPB>>>(ei, Wh, bh, Wo, bo);
    k_exp<<<eblocks, TPB>>>(ei);
    k_soft<<<eblocks, TPB>>>(ei);
    for (int t = 0; t < MAXIT; t++) {
        k_A<<<nblocks, TPB>>>(ei, t);
        k_B<<<nblocks, TPB>>>(t);
        k_E<<<2048, TPB>>>(ei, t);
    }
    k_out<<<2048, TPB>>>(ei, out);
}

// round 6
// speedup vs baseline: 1.2850x; 1.1171x over previous
#include <cuda_runtime.h>

#define NN 100000
#define EE 1600000
#define CC 16
#define HH 32
#define NLAY 8
#define TPB 256
#define MTPB 128
#define MAXIT 10
#define THRESH 5000   // count <= 5000  <=>  ratio <= 0.05 (exact in fp32)

// ---------------- device scratch ----------------
__device__ unsigned int        g_mkey[NN];
__device__ double              g_ssum[NN];
__device__ float               g_tmp[EE];
__device__ float               g_score[EE];
__device__ unsigned long long  g_packs[NN];
__device__ unsigned long long  g_packd[NN];
__device__ int                 g_maxidx[NN];
__device__ int                 g_part[NN];
__device__ unsigned char       g_nrem[NN];
__device__ unsigned char       g_rm[NN];
__device__ int                 g_cnt[MAXIT];
__device__ int                 g_lc[2];
__device__ int4                g_list[2][EE];
__device__ float               g_P[NN * HH];   // x @ W0[:16] + b0  (src half)
__device__ float               g_Q[NN * HH];   // x @ W0[16:]       (dst half)

__device__ __forceinline__ unsigned int fkey(float f) {
    unsigned int b = __float_as_uint(f);
    return (b & 0x80000000u) ? ~b : (b | 0x80000000u);
}
__device__ __forceinline__ float fkey_inv(unsigned int k) {
    unsigned int b = (k & 0x80000000u) ? (k ^ 0x80000000u) : ~k;
    return __uint_as_float(b);
}
__device__ __forceinline__ bool iter_done(int t) {
    return (t > 0) && (g_cnt[t - 1] <= THRESH);
}

// ---------------- layer-1 per-node precompute + global init (fused) ----------------
__global__ void __launch_bounds__(TPB)
k_pre(const float* __restrict__ x, const float* __restrict__ Wh,
      const float* __restrict__ bh) {
    __shared__ __align__(16) float W0[HH * HH];
    __shared__ float b0[HH];
    for (int i = threadIdx.x; i < HH * HH; i += blockDim.x) W0[i] = Wh[i];
    if (threadIdx.x < HH) b0[threadIdx.x] = bh[threadIdx.x];
    __syncthreads();

    int n = blockIdx.x * blockDim.x + threadIdx.x;

    // global-state init (fused former k_init)
    if (n < NN) {
        g_mkey[n] = 0u;
        g_ssum[n] = 0.0;
        g_packs[n] = 0ull;       // score=0.0f, eid=E (matches empty-segment fill)
        g_packd[n] = 0ull;
        g_nrem[n] = 1;
        g_rm[n] = 0;
        g_part[n] = -1;
    }
    if (n < MAXIT) g_cnt[n] = 0;
    if (n < 2) g_lc[n] = 0;

    if (n >= NN) return;

    float xv[CC];
    const float4* xp = (const float4*)(x + (size_t)n * CC);
#pragma unroll
    for (int q = 0; q < 4; q++) {
        float4 v = xp[q];
        xv[4 * q] = v.x; xv[4 * q + 1] = v.y; xv[4 * q + 2] = v.z; xv[4 * q + 3] = v.w;
    }
    float a[HH];
#pragma unroll
    for (int j = 0; j < HH; j++) a[j] = b0[j];
#pragma unroll
    for (int k = 0; k < CC; k++) {
        float xk = xv[k];
        const float4* w4 = (const float4*)(W0 + k * HH);
#pragma unroll
        for (int j = 0; j < HH / 4; j++) {
            float4 w = w4[j];
            a[4 * j] = fmaf(xk, w.x, a[4 * j]);
            a[4 * j + 1] = fmaf(xk, w.y, a[4 * j + 1]);
            a[4 * j + 2] = fmaf(xk, w.z, a[4 * j + 2]);
            a[4 * j + 3] = fmaf(xk, w.w, a[4 * j + 3]);
        }
    }
    float4* Pp = (float4*)(g_P + (size_t)n * HH);
#pragma unroll
    for (int j = 0; j < HH / 4; j++)
        Pp[j] = make_float4(a[4 * j], a[4 * j + 1], a[4 * j + 2], a[4 * j + 3]);

#pragma unroll
    for (int j = 0; j < HH; j++) a[j] = 0.0f;
#pragma unroll
    for (int k = 0; k < CC; k++) {
        float xk = xv[k];
        const float4* w4 = (const float4*)(W0 + (CC + k) * HH);
#pragma unroll
        for (int j = 0; j < HH / 4; j++) {
            float4 w = w4[j];
            a[4 * j] = fmaf(xk, w.x, a[4 * j]);
            a[4 * j + 1] = fmaf(xk, w.y, a[4 * j + 1]);
            a[4 * j + 2] = fmaf(xk, w.z, a[4 * j + 2]);
            a[4 * j + 3] = fmaf(xk, w.w, a[4 * j + 3]);
        }
    }
    float4* Qp = (float4*)(g_Q + (size_t)n * HH);
#pragma unroll
    for (int j = 0; j < HH / 4; j++)
        Qp[j] = make_float4(a[4 * j], a[4 * j + 1], a[4 * j + 2], a[4 * j + 3]);
}

// ---------------- edge MLP layers 2..8, 2 edges per thread ----------------
// Arithmetic is bit-identical to the round-3 kernel: per output neuron,
// acc = bias; k ascending fmaf chain; relu; final dot sequential.
__global__ void __launch_bounds__(MTPB)
k_mlp(const int* __restrict__ ei,
      const float* __restrict__ Wh, const float* __restrict__ bh,
      const float* __restrict__ Wo, const float* __restrict__ bo) {
    __shared__ __align__(16) float Wsh[(NLAY - 1) * HH * HH];  // layers 1..7 (28 KB)
    __shared__ float bsh[(NLAY - 1) * HH];
    __shared__ float Wosh[HH];
    __shared__ float bosh;
    for (int i = threadIdx.x; i < (NLAY - 1) * HH * HH; i += blockDim.x)
        Wsh[i] = Wh[HH * HH + i];
    for (int i = threadIdx.x; i < (NLAY - 1) * HH; i += blockDim.x)
        bsh[i] = bh[HH + i];
    if (threadIdx.x < HH) Wosh[threadIdx.x] = Wo[threadIdx.x];
    if (threadIdx.x == 0) bosh = bo[0];
    __syncthreads();

    int i = blockIdx.x * MTPB + threadIdx.x;   // 0 .. EE/2-1
    int eA = i;
    int eB = i + (EE / 2);
    int sA = ei[eA], dA = ei[EE + eA];
    int sB = ei[eB], dB = ei[EE + eB];

    float h[2][HH];
    {
        const float4* PA = (const float4*)(g_P + (size_t)sA * HH);
        const float4* QA = (const float4*)(g_Q + (size_t)dA * HH);
        const float4* PB = (const float4*)(g_P + (size_t)sB * HH);
        const float4* QB = (const float4*)(g_Q + (size_t)dB * HH);
#pragma unroll
        for (int q = 0; q < HH / 4; q++) {
            float4 pa = PA[q], qa = QA[q];
            float4 pb = PB[q], qb = QB[q];
            h[0][4 * q + 0] = fmaxf(pa.x + qa.x, 0.0f);
            h[0][4 * q + 1] = fmaxf(pa.y + qa.y, 0.0f);
            h[0][4 * q + 2] = fmaxf(pa.z + qa.z, 0.0f);
            h[0][4 * q + 3] = fmaxf(pa.w + qa.w, 0.0f);
            h[1][4 * q + 0] = fmaxf(pb.x + qb.x, 0.0f);
            h[1][4 * q + 1] = fmaxf(pb.y + qb.y, 0.0f);
            h[1][4 * q + 2] = fmaxf(pb.z + qb.z, 0.0f);
            h[1][4 * q + 3] = fmaxf(pb.w + qb.w, 0.0f);
        }
    }

#pragma unroll 1
    for (int l = 0; l < NLAY - 1; l++) {
        float o[2][HH];
#pragma unroll
        for (int j = 0; j < HH; j++) {
            float bb = bsh[l * HH + j];
            o[0][j] = bb;
            o[1][j] = bb;
        }
        const float* Wl = Wsh + l * HH * HH;
#pragma unroll
        for (int k = 0; k < HH; k++) {
            float hA = h[0][k], hB = h[1][k];
            const float4* w4 = (const float4*)(Wl + k * HH);
#pragma unroll
            for (int j = 0; j < HH / 4; j++) {
                float4 w = w4[j];
                o[0][4 * j + 0] = fmaf(hA, w.x, o[0][4 * j + 0]);
                o[0][4 * j + 1] = fmaf(hA, w.y, o[0][4 * j + 1]);
                o[0][4 * j + 2] = fmaf(hA, w.z, o[0][4 * j + 2]);
                o[0][4 * j + 3] = fmaf(hA, w.w, o[0][4 * j + 3]);
                o[1][4 * j + 0] = fmaf(hB, w.x, o[1][4 * j + 0]);
                o[1][4 * j + 1] = fmaf(hB, w.y, o[1][4 * j + 1]);
                o[1][4 * j + 2] = fmaf(hB, w.z, o[1][4 * j + 2]);
                o[1][4 * j + 3] = fmaf(hB, w.w, o[1][4 * j + 3]);
            }
        }
#pragma unroll
        for (int j = 0; j < HH; j++) {
            h[0][j] = fmaxf(o[0][j], 0.0f);
            h[1][j] = fmaxf(o[1][j], 0.0f);
        }
    }

    float accA = bosh, accB = bosh;
#pragma unroll
    for (int k = 0; k < HH; k++) {
        float w = Wosh[k];
        accA = fmaf(h[0][k], w, accA);
        accB = fmaf(h[1][k], w, accB);
    }

    g_tmp[eA] = accA;
    atomicMax(&g_mkey[dA], fkey(accA));
    g_tmp[eB] = accB;
    atomicMax(&g_mkey[dB], fkey(accB));
}

// ---------------- exp + segment sum ----------------
__global__ void k_exp(const int* __restrict__ ei) {
    int e = blockIdx.x * blockDim.x + threadIdx.x;
    if (e >= EE) return;
    int d = ei[EE + e];
    float m = fkey_inv(g_mkey[d]);
    float ex = expf(g_tmp[e] - m);
    g_tmp[e] = ex;
    atomicAdd(&g_ssum[d], (double)ex);
}

// ---------------- softmax finalize + iteration-0 pack accumulation ----------------
__global__ void k_soft(const int* __restrict__ ei) {
    int e = blockIdx.x * blockDim.x + threadIdx.x;
    if (e >= EE) return;
    int s = ei[e], d = ei[EE + e];
    float sc = g_tmp[e] / (float)g_ssum[d] + 0.5f;
    g_score[e] = sc;
    unsigned long long pk =
        ((unsigned long long)__float_as_uint(sc) << 32) | (unsigned int)(EE - e);
    atomicMax(&g_packs[s], pk);
    atomicMax(&g_packd[d], pk);
}

// ---------------- merge A: apply pending removal; maxidx from packs ----------------
__global__ void k_A(const int* __restrict__ ei, int t) {
    if (iter_done(t)) return;
    int n = blockIdx.x * blockDim.x + threadIdx.x;
    if (n == 0) g_lc[(t + 1) & 1] = 0;
    if (n >= NN) return;
    if (g_rm[n]) g_nrem[n] = 0;     // commit iteration t-1 (rm==0 at t=0)
    unsigned long long p0 = g_packs[n], p1 = g_packd[n];
    g_packs[n] = 0ull; g_packd[n] = 0ull;
    float ms0 = __uint_as_float((unsigned int)(p0 >> 32));
    float ms1 = __uint_as_float((unsigned int)(p1 >> 32));
    int mi = 0;
    if (ms1 > ms0) {
        int eid = EE - (int)(unsigned int)(p1 & 0xFFFFFFFFull);
        eid = min(eid, EE - 1);
        mi = ei[eid];            // src[am1]
    } else if (ms0 > ms1) {
        int eid = EE - (int)(unsigned int)(p0 & 0xFFFFFFFFull);
        eid = min(eid, EE - 1);
        mi = ei[EE + eid];       // dst[am0]
    }
    g_maxidx[n] = mi;
}

// ---------------- merge B: mutual-match flag + partner + survivor count ----------------
__global__ void k_B(int t) {
    if (iter_done(t)) return;
    int n = blockIdx.x * blockDim.x + threadIdx.x;
    int surv = 0;
    if (n < NN) {
        int v = g_maxidx[n];
        bool nr = g_nrem[n];
        bool rm = nr && g_nrem[v] && (g_maxidx[v] == n);
        g_rm[n] = rm ? 1 : 0;
        if (rm) g_part[n] = v;
        surv = (nr && !rm) ? 1 : 0;
    }
    unsigned m = __ballot_sync(0xffffffffu, surv);
    if ((threadIdx.x & 31) == 0 && m)
        atomicAdd(&g_cnt[t], __popc(m));
}

// ---------------- merge E: compact live list + accumulate next packs ----------------
__global__ void k_E(const int* __restrict__ ei, int t) {
    if (iter_done(t)) return;
    if (t == MAXIT - 1 || g_cnt[t] <= THRESH) return;

    int total = (t == 0) ? EE : g_lc[t & 1];
    int lane = threadIdx.x & 31;
    int stride = gridDim.x * blockDim.x;
    int start = blockIdx.x * blockDim.x + threadIdx.x;
    int iters = (total + stride - 1) / stride;
    int outp = (t + 1) & 1;

    for (int it = 0; it < iters; it++) {
        int i = start + it * stride;
        bool inb = i < total;
        int4 rec;
        if (inb) {
            if (t == 0) {
                rec.x = ei[i];
                rec.y = ei[EE + i];
                rec.z = i;
                rec.w = __float_as_int(g_score[i]);
            } else {
                rec = g_list[t & 1][i];
            }
        }
        bool live = inb && g_nrem[rec.x] && !g_rm[rec.x]
                        && g_nrem[rec.y] && !g_rm[rec.y];
        unsigned mask = __ballot_sync(0xffffffffu, live);
        if (mask) {
            int leader = __ffs(mask) - 1;
            int base;
            if (lane == leader) base = atomicAdd(&g_lc[outp], __popc(mask));
            base = __shfl_sync(0xffffffffu, base, leader);
            if (live) {
                int off = __popc(mask & ((1u << lane) - 1));
                g_list[outp][base + off] = rec;
                unsigned long long pk =
                    ((unsigned long long)(unsigned int)rec.w << 32) |
                    (unsigned int)(EE - rec.z);
                atomicMax(&g_packs[rec.x], pk);
                atomicMax(&g_packd[rec.y], pk);
            }
        }
    }
}

// ---------------- output ----------------
__global__ void k_out(const int* __restrict__ ei, float* __restrict__ out) {
    int i = blockIdx.x * blockDim.x + threadIdx.x;
    int stride = gridDim.x * blockDim.x;
    for (int e = i; e < EE; e += stride) {
        int s = ei[e], d = ei[EE + e];
        bool live = g_nrem[s] && !g_rm[s] && g_nrem[d] && !g_rm[d];
        out[e] = live ? g_score[e] : 0.0f;
        bool removed = (g_part[s] == d) && (g_part[d] == s);
        out[EE + e] = removed ? 0.0f : 1.0f;
    }
    for (int n = i; n < NN; n += stride) {
        out[2 * EE + n] = (g_nrem[n] && !g_rm[n]) ? 1.0f : 0.0f;
    }
}

extern "C" void kernel_launch(void* const* d_in, const int* in_sizes, int n_in,
                              void* d_out, int out_size) {
    const float* x  = (const float*)d_in[0];
    const int*   ei = (const int*)d_in[1];
    // d_in[2] = batch (unused, all zeros)
    const float* Wh = (const float*)d_in[3];
    const float* bh = (const float*)d_in[4];
    const float* Wo = (const float*)d_in[5];
    const float* bo = (const float*)d_in[6];
    float* out = (float*)d_out;

    const int eblocks = (EE + TPB - 1) / TPB;
    const int nblocks = (NN + TPB - 1) / TPB;
    const int mblocks = (EE / 2) / MTPB;   // 6250

    k_pre<<<nblocks, TPB>>>(x, Wh, bh);
    k_mlp<<<mblocks, MTPB>>>(ei, Wh, bh, Wo, bo);
    k_exp<<<eblocks, TPB>>>(ei);
    k_soft<<<eblocks, TPB>>>(ei);
    for (int t = 0; t < MAXIT; t++) {
        k_A<<<nblocks, TPB>>>(ei, t);
        k_B<<<nblocks, TPB>>>(t);
        k_E<<<2048, TPB>>>(ei, t);
    }
    k_out<<<2048, TPB>>>(ei, out);
}